// round 14
// baseline (speedup 1.0000x reference)
#include <cuda_runtime.h>
#include <math.h>

#define HC 64
#define NF 64
#define NG 5
#define SL 20
#define ZD 148
#define BN_EPS 1e-5f
#define MAX_N 50000
#define MAX_E 800000

typedef unsigned long long ull;

// Scratch (allocation-free rule: __device__ globals)
__device__ __align__(16) float g_agg[MAX_N * NF];        // per-layer aggregation
__device__ __align__(16) float g_proj[MAX_N * 4 * NF];   // [N][Af|Bf|As|Bs] fp32
__device__ __align__(16) float g_ea[(size_t)MAX_E * SL]; // relu(edge_attr@short_w), BUCKET order
__device__ __align__(16) float g_sums[2 * NF];           // sum / sumsq
__device__ int g_deg[MAX_N];
__device__ int g_off[MAX_N];
__device__ int g_cur[MAX_N];
__device__ int g_pos[MAX_E];   // edge id -> bucket position
__device__ int g_srcb[MAX_E];  // src node, bucket order

// ---------------- packed f32x2 helpers ----------------
__device__ __forceinline__ ull fma2(ull a, ull b, ull c) {
    ull d;
    asm("fma.rn.f32x2 %0, %1, %2, %3;" : "=l"(d) : "l"(a), "l"(b), "l"(c));
    return d;
}
__device__ __forceinline__ ull add2(ull a, ull b) {
    ull d;
    asm("add.rn.f32x2 %0, %1, %2;" : "=l"(d) : "l"(a), "l"(b));
    return d;
}
__device__ __forceinline__ ull pack2(float v) {
    ull r;
    asm("mov.b64 %0, {%1, %1};" : "=l"(r) : "f"(v));
    return r;
}
__device__ __forceinline__ float2 unpack2(ull v) {
    float2 r;
    asm("mov.b64 {%0, %1}, %2;" : "=f"(r.x), "=f"(r.y) : "l"(v));
    return r;
}
// pack two fp32 into bf16x2 word (lo -> low half), round-to-nearest
__device__ __forceinline__ unsigned f2_to_bf2(float lo, float hi) {
    unsigned r;
    asm("cvt.rn.bf16x2.f32 %0, %1, %2;" : "=r"(r) : "f"(hi), "f"(lo));
    return r;
}
// expand bf16x2 word -> packed f32x2 (shift for low lane; raw word as high)
__device__ __forceinline__ ull bf2_to_f32x2(unsigned p) {
    unsigned lo = p << 16;
    ull r;
    asm("mov.b64 %0, {%1, %2};" : "=l"(r) : "r"(lo), "r"(p));
    return r;
}
__device__ __forceinline__ float sigmoid_t(float x) {
    float t;
    asm("tanh.approx.f32 %0, %1;" : "=f"(t) : "f"(0.5f * x));
    return fmaf(0.5f, t, 0.5f);
}
__device__ __forceinline__ float msg_fn(float f, float s) {
    float sp = fmaxf(s, 0.f) + __logf(1.f + __expf(-fabsf(s)));
    return sigmoid_t(f) * sp;
}

// ---------------------------------------------------------------------------
// Launch 1: fused [zero_deg | lin0]
#define K1_ZB 64
#define K1_LB 592

__global__ __launch_bounds__(256) void pre_kernel(
    const float* __restrict__ h, const float* __restrict__ W,
    const float* __restrict__ b, float* __restrict__ out, int N)
{
    int tid = threadIdx.x;
    int blk = blockIdx.x;
    if (blk < K1_ZB) {
        int stride = K1_ZB * 256;
        for (int i = blk * 256 + tid; i < N; i += stride) g_deg[i] = 0;
        return;
    }
    blk -= K1_ZB;
    __shared__ float sW[64 * 64];
    __shared__ float sb[64];
    for (int i = tid; i < 64 * 64; i += 256) sW[i] = W[i];
    if (tid < 64) sb[tid] = b[tid];
    __syncthreads();
    int c = tid & 63, rr = tid >> 6;
    for (int r0 = blk * 4; r0 < N; r0 += K1_LB * 4) {
        int r = r0 + rr;
        if (r < N) {
            const float* hr = h + (size_t)r * 64;
            float acc = sb[c];
#pragma unroll 16
            for (int k = 0; k < 64; k++)
                acc = fmaf(__ldg(hr + k), sW[k * 64 + c], acc);
            out[(size_t)r * 64 + c] = fmaxf(acc, 0.f);
        }
    }
}

// ---------------------------------------------------------------------------
__global__ __launch_bounds__(256) void hist_kernel(const int* __restrict__ ei, int E) {
    int stride = gridDim.x * blockDim.x;
    for (int e = blockIdx.x * blockDim.x + threadIdx.x; e < E; e += stride)
        atomicAdd(&g_deg[__ldg(ei + E + e)], 1);
}

__global__ __launch_bounds__(1024) void scan_kernel(int N) {
    __shared__ int part[1024];
    int t = threadIdx.x;
    int C = (N + 1023) >> 10;
    int lo = t * C, hi = min(lo + C, N);
    int s = 0;
    for (int i = lo; i < hi; i++) s += g_deg[i];
    part[t] = s;
    __syncthreads();
    for (int d = 1; d < 1024; d <<= 1) {
        int v = (t >= d) ? part[t - d] : 0;
        __syncthreads();
        part[t] += v;
        __syncthreads();
    }
    int run = part[t] - s;
    for (int i = lo; i < hi; i++) {
        int d = g_deg[i];
        g_off[i] = run;
        g_cur[i] = run;
        run += d;
    }
}

__global__ __launch_bounds__(256) void scatter_kernel(const int* __restrict__ ei, int E) {
    int stride = gridDim.x * blockDim.x;
    for (int e = blockIdx.x * blockDim.x + threadIdx.x; e < E; e += stride) {
        int dst = __ldg(ei + E + e);
        int pos = atomicAdd(&g_cur[dst], 1);
        g_pos[e] = pos;
        g_srcb[pos] = __ldg(ei + e);
    }
}

// ---------------------------------------------------------------------------
// g_ea[pos(e)] = relu(edge_attr[e] @ short_w + short_b)  (bucket-order write)
__global__ __launch_bounds__(256) void ea_kernel(
    const float* __restrict__ attr, const float* __restrict__ sw,
    const float* __restrict__ sb, int E)
{
    __shared__ float w[NG * SL];
    __shared__ float b[SL];
    int tid = threadIdx.x;
    if (tid < NG * SL) w[tid] = sw[tid];
    if (tid < SL)      b[tid] = sb[tid];
    __syncthreads();
    int stride = gridDim.x * blockDim.x;
    for (int e = blockIdx.x * blockDim.x + tid; e < E; e += stride) {
        float a[NG];
#pragma unroll
        for (int g = 0; g < NG; g++) a[g] = __ldg(attr + (size_t)e * NG + g);
        float4* dst = (float4*)(g_ea + (size_t)__ldg(&g_pos[e]) * SL);
#pragma unroll
        for (int q = 0; q < 5; q++) {
            float o[4];
#pragma unroll
            for (int j = 0; j < 4; j++) {
                float acc = b[q * 4 + j];
#pragma unroll
                for (int g = 0; g < NG; g++)
                    acc = fmaf(a[g], w[g * SL + q * 4 + j], acc);
                o[j] = fmaxf(acc, 0.f);
            }
            dst[q] = make_float4(o[0], o[1], o[2], o[3]);
        }
    }
}

// ---------------------------------------------------------------------------
// g_proj[n] = out[n] @ [W1f | W2f | W1s | W2s]  (+bf on Af, +bs on As)
// Layout per node (256 floats): [Af | Bf | As | Bs].
// Block 0 zeroes g_sums for the coming layer.
__global__ __launch_bounds__(256) void node_proj_kernel(
    const float* __restrict__ out,
    const float* __restrict__ Wf, const float* __restrict__ bf,
    const float* __restrict__ Ws, const float* __restrict__ bs,
    int N)
{
    int tid = threadIdx.x;
    if (blockIdx.x == 0 && tid < 2 * NF) g_sums[tid] = 0.f;

    __shared__ __align__(16) float sOut[16 * 64];
    int c = tid;
    const float* base; int col; float bias;
    if (c < 64)       { base = Wf;           col = c;        bias = __ldg(bf + c); }
    else if (c < 128) { base = Wf + 64 * 64; col = c - 64;   bias = 0.f; }
    else if (c < 192) { base = Ws;           col = c - 128;  bias = __ldg(bs + c - 128); }
    else              { base = Ws + 64 * 64; col = c - 192;  bias = 0.f; }
    float w[64];
#pragma unroll
    for (int k = 0; k < 64; k++) w[k] = __ldg(base + k * 64 + col);

    for (int r0 = blockIdx.x * 16; r0 < N; r0 += gridDim.x * 16) {
        __syncthreads();
        for (int i = tid; i < 16 * 16; i += 256) {
            int r = i >> 4, q = i & 15;
            int rr = r0 + r;
            float4 v = (rr < N) ? ((const float4*)out)[(size_t)rr * 16 + q]
                                : make_float4(0.f, 0.f, 0.f, 0.f);
            ((float4*)sOut)[r * 16 + q] = v;
        }
        __syncthreads();
        float acc[16];
#pragma unroll
        for (int r = 0; r < 16; r++) acc[r] = bias;
#pragma unroll
        for (int k4 = 0; k4 < 16; k4++) {
#pragma unroll
            for (int r = 0; r < 16; r++) {
                float4 z = ((const float4*)sOut)[r * 16 + k4];
                acc[r] = fmaf(z.x, w[k4 * 4 + 0], acc[r]);
                acc[r] = fmaf(z.y, w[k4 * 4 + 1], acc[r]);
                acc[r] = fmaf(z.z, w[k4 * 4 + 2], acc[r]);
                acc[r] = fmaf(z.w, w[k4 * 4 + 3], acc[r]);
            }
        }
#pragma unroll
        for (int r = 0; r < 16; r++) {
            int rr = r0 + r;
            if (rr < N) g_proj[(size_t)rr * 256 + c] = acc[r];
        }
    }
}

// ---------------------------------------------------------------------------
// edge_agg: one warp per node; dst terms (Af/As) loaded ONCE per node.
// 4 bucket entries per warp-iter (half-split, champion inner loop with bf16
// interleaved smem weights). Register accumulation -> single coalesced store.
// BN stats fused (per-lane running sums; 8 atomics per warp at exit).
__global__ __launch_bounds__(256) void edge_agg_kernel(
    const float* __restrict__ W3f, const float* __restrict__ W3s, int N)
{
    __shared__ __align__(16) uint4 sWH[SL * 16];
    int tid = threadIdx.x;
    for (int i = tid; i < SL * 16; i += 256) {
        int k = i >> 4, t4 = (i & 15) * 4;
        const float* wf = W3f + k * 64 + t4;
        const float* ws = W3s + k * 64 + t4;
        uint4 v;
        v.x = f2_to_bf2(__ldg(wf + 0), __ldg(wf + 1));
        v.y = f2_to_bf2(__ldg(wf + 2), __ldg(wf + 3));
        v.z = f2_to_bf2(__ldg(ws + 0), __ldg(ws + 1));
        v.w = f2_to_bf2(__ldg(ws + 2), __ldg(ws + 3));
        sWH[i] = v;
    }
    __syncthreads();

    int lane = tid & 31;
    int t = lane & 15;
    int half = lane >> 4;

    int warp  = (blockIdx.x * 256 + tid) >> 5;
    int nwarp = gridDim.x * 8;

    float s0 = 0.f, s1 = 0.f, s2 = 0.f, s3 = 0.f;      // BN sum (lanes<16 valid)
    float q0 = 0.f, q1 = 0.f, q2 = 0.f, q3 = 0.f;      // BN sumsq

    for (int n = warp; n < N; n += nwarp) {
        int beg = __ldg(&g_off[n]);
        int end = beg + __ldg(&g_deg[n]);

        const ulonglong2* pd = (const ulonglong2*)(g_proj + (size_t)n * 256);
        ulonglong2 afd = __ldg(pd + t);        // Af (bias incl.)
        ulonglong2 asd = __ldg(pd + 32 + t);   // As (bias incl.)

        float a0 = 0.f, a1 = 0.f, a2 = 0.f, a3 = 0.f;

        for (int i = beg; i < end; i += 4) {
            int eA = i + half;
            int eB = i + 2 + half;
            bool vA = eA < end, vB = eB < end;
            int eAc = vA ? eA : beg;
            int eBc = vB ? eB : beg;

            int srcA = __ldg(&g_srcb[eAc]);
            int srcB = __ldg(&g_srcb[eBc]);

            const float4* pa = (const float4*)(g_ea + (size_t)eAc * SL);
            const float4* pb = (const float4*)(g_ea + (size_t)eBc * SL);
            float4 A0 = __ldg(pa), A1 = __ldg(pa + 1), A2 = __ldg(pa + 2),
                   A3 = __ldg(pa + 3), A4 = __ldg(pa + 4);
            float4 B0 = __ldg(pb), B1 = __ldg(pb + 1), B2 = __ldg(pb + 2),
                   B3 = __ldg(pb + 3), B4 = __ldg(pb + 4);
            float eaA[20] = {A0.x, A0.y, A0.z, A0.w, A1.x, A1.y, A1.z, A1.w,
                             A2.x, A2.y, A2.z, A2.w, A3.x, A3.y, A3.z, A3.w,
                             A4.x, A4.y, A4.z, A4.w};
            float eaB[20] = {B0.x, B0.y, B0.z, B0.w, B1.x, B1.y, B1.z, B1.w,
                             B2.x, B2.y, B2.z, B2.w, B3.x, B3.y, B3.z, B3.w,
                             B4.x, B4.y, B4.z, B4.w};

            const ulonglong2* psA = (const ulonglong2*)(g_proj + (size_t)srcA * 256);
            const ulonglong2* psB = (const ulonglong2*)(g_proj + (size_t)srcB * 256);
            ulonglong2 bfA = __ldg(psA + 16 + t), bsA = __ldg(psA + 48 + t);
            ulonglong2 bfB = __ldg(psB + 16 + t), bsB = __ldg(psB + 48 + t);

            ull fA01 = add2(afd.x, bfA.x), fA23 = add2(afd.y, bfA.y);
            ull sA01 = add2(asd.x, bsA.x), sA23 = add2(asd.y, bsA.y);
            ull fB01 = add2(afd.x, bfB.x), fB23 = add2(afd.y, bfB.y);
            ull sB01 = add2(asd.x, bsB.x), sB23 = add2(asd.y, bsB.y);

#pragma unroll 4
            for (int k = 0; k < SL; k++) {
                uint4 wp = sWH[k * 16 + t];
                ull wf01 = bf2_to_f32x2(wp.x);
                ull wf23 = bf2_to_f32x2(wp.y);
                ull ws01 = bf2_to_f32x2(wp.z);
                ull ws23 = bf2_to_f32x2(wp.w);
                ull aA = pack2(eaA[k]);
                ull aB = pack2(eaB[k]);
                fA01 = fma2(aA, wf01, fA01);
                fA23 = fma2(aA, wf23, fA23);
                sA01 = fma2(aA, ws01, sA01);
                sA23 = fma2(aA, ws23, sA23);
                fB01 = fma2(aB, wf01, fB01);
                fB23 = fma2(aB, wf23, fB23);
                sB01 = fma2(aB, ws01, sB01);
                sB23 = fma2(aB, ws23, sB23);
            }

            if (vA) {
                float2 F0 = unpack2(fA01), F1 = unpack2(fA23);
                float2 S0 = unpack2(sA01), S1 = unpack2(sA23);
                a0 += msg_fn(F0.x, S0.x);
                a1 += msg_fn(F0.y, S0.y);
                a2 += msg_fn(F1.x, S1.x);
                a3 += msg_fn(F1.y, S1.y);
            }
            if (vB) {
                float2 F0 = unpack2(fB01), F1 = unpack2(fB23);
                float2 S0 = unpack2(sB01), S1 = unpack2(sB23);
                a0 += msg_fn(F0.x, S0.x);
                a1 += msg_fn(F0.y, S0.y);
                a2 += msg_fn(F1.x, S1.x);
                a3 += msg_fn(F1.y, S1.y);
            }
        }

        // combine halves: lanes 0-15 get half1's partial from lanes 16-31
        a0 += __shfl_down_sync(0xffffffff, a0, 16);
        a1 += __shfl_down_sync(0xffffffff, a1, 16);
        a2 += __shfl_down_sync(0xffffffff, a2, 16);
        a3 += __shfl_down_sync(0xffffffff, a3, 16);

        if (lane < 16) {
            ((float4*)g_agg)[(size_t)n * 16 + t] = make_float4(a0, a1, a2, a3);
            s0 += a0; s1 += a1; s2 += a2; s3 += a3;
            q0 = fmaf(a0, a0, q0); q1 = fmaf(a1, a1, q1);
            q2 = fmaf(a2, a2, q2); q3 = fmaf(a3, a3, q3);
        }
    }

    if (lane < 16) {
        int c0 = t * 4;
        atomicAdd(&g_sums[c0 + 0], s0);
        atomicAdd(&g_sums[c0 + 1], s1);
        atomicAdd(&g_sums[c0 + 2], s2);
        atomicAdd(&g_sums[c0 + 3], s3);
        atomicAdd(&g_sums[64 + c0 + 0], q0);
        atomicAdd(&g_sums[64 + c0 + 1], q1);
        atomicAdd(&g_sums[64 + c0 + 2], q2);
        atomicAdd(&g_sums[64 + c0 + 3], q3);
    }
}

// ---------------------------------------------------------------------------
// out = out + relu( BN(agg) + out )
__global__ __launch_bounds__(256) void bn_apply_kernel(
    const float* __restrict__ gamma, const float* __restrict__ beta,
    float* __restrict__ out, int N, float invN)
{
    int tid = threadIdx.x;
    int c0 = (tid & 15) * 4;
    float mul[4], add[4];
#pragma unroll
    for (int j = 0; j < 4; j++) {
        float mean = g_sums[c0 + j] * invN;
        float var  = fmaf(-mean, mean, g_sums[64 + c0 + j] * invN);
        float inv  = rsqrtf(var + BN_EPS);
        float m = inv * __ldg(gamma + c0 + j);
        mul[j] = m;
        add[j] = __ldg(beta + c0 + j) - mean * m;
    }
    float4* o4 = (float4*)out;
    const float4* a4 = (const float4*)g_agg;
    int total = N * 16;
    int stride = gridDim.x * 256;
    for (int i = blockIdx.x * 256 + tid; i < total; i += stride) {
        float4 a = a4[i], o = o4[i], r;
        float bn;
        bn = fmaf(a.x, mul[0], add[0]); r.x = o.x + fmaxf(bn + o.x, 0.f);
        bn = fmaf(a.y, mul[1], add[1]); r.y = o.y + fmaxf(bn + o.y, 0.f);
        bn = fmaf(a.z, mul[2], add[2]); r.z = o.z + fmaxf(bn + o.z, 0.f);
        bn = fmaf(a.w, mul[3], add[3]); r.w = o.w + fmaxf(bn + o.w, 0.f);
        o4[i] = r;
    }
}

// ---------------------------------------------------------------------------
extern "C" void kernel_launch(void* const* d_in, const int* in_sizes, int n_in,
                              void* d_out, int out_size)
{
    const float* h      = (const float*)d_in[0];
    const int*   ei     = (const int*)  d_in[1];
    // d_in[2] = edge_weight (unused by reference)
    const float* eattr  = (const float*)d_in[3];
    const float* lin0_w = (const float*)d_in[4];
    const float* lin0_b = (const float*)d_in[5];
    const float* shw    = (const float*)d_in[6];
    const float* shb    = (const float*)d_in[7];
    const float* linf_w = (const float*)d_in[8];
    const float* linf_b = (const float*)d_in[9];
    const float* lins_w = (const float*)d_in[10];
    const float* lins_b = (const float*)d_in[11];
    const float* gamma  = (const float*)d_in[12];
    const float* beta   = (const float*)d_in[13];

    int N = in_sizes[0] / HC;
    int E = in_sizes[1] / 2;
    float* out = (float*)d_out;
    float invN = 1.f / (float)N;

    const float* Wf0 = linf_w;
    const float* Ws0 = lins_w;
    const float* Wf1 = linf_w + (size_t)ZD * NF;
    const float* Ws1 = lins_w + (size_t)ZD * NF;

    // preprocessing
    pre_kernel<<<K1_ZB + K1_LB, 256>>>(h, lin0_w, lin0_b, out, N);   // 1
    hist_kernel<<<1480, 256>>>(ei, E);                                // 2
    scan_kernel<<<1, 1024>>>(N);                                      // 3
    scatter_kernel<<<1480, 256>>>(ei, E);                             // 4
    ea_kernel<<<1184, 256>>>(eattr, shw, shb, E);                     // 5

    // ---- layer 0 ----
    node_proj_kernel<<<592, 256>>>(out, Wf0, linf_b, Ws0, lins_b, N); // 6
    edge_agg_kernel<<<1184, 256>>>(Wf0 + 128 * NF, Ws0 + 128 * NF, N);// 7
    bn_apply_kernel<<<592, 256>>>(gamma, beta, out, N, invN);         // 8

    // ---- layer 1 ----
    node_proj_kernel<<<592, 256>>>(out, Wf1, linf_b + NF, Ws1, lins_b + NF, N); // 9
    edge_agg_kernel<<<1184, 256>>>(Wf1 + 128 * NF, Ws1 + 128 * NF, N);          // 10
    bn_apply_kernel<<<592, 256>>>(gamma + NF, beta + NF, out, N, invN);         // 11
}

// round 15
// speedup vs baseline: 1.5341x; 1.5341x over previous
#include <cuda_runtime.h>
#include <math.h>

#define HC 64
#define NF 64
#define NG 5
#define SL 20
#define ZD 148
#define BN_EPS 1e-5f
#define MAX_N 50000
#define MAX_E 800000
#define EP (MAX_E + 8)   // padded edge stride for transposed ea

typedef unsigned long long ull;

// Scratch (allocation-free rule: __device__ globals)
__device__ __align__(16) float g_agg[MAX_N * NF];        // per-layer aggregation
__device__ __align__(16) float g_proj[MAX_N * 4 * NF];   // [N][Af|Bf|As|Bs] fp32
__device__ __align__(16) float g_eat[(size_t)SL * EP];   // TRANSPOSED ea: [k][e]
__device__ __align__(16) float g_sums[2 * NF];           // sum / sumsq

// ---------------- packed f32x2 helpers ----------------
__device__ __forceinline__ ull fma2(ull a, ull b, ull c) {
    ull d;
    asm("fma.rn.f32x2 %0, %1, %2, %3;" : "=l"(d) : "l"(a), "l"(b), "l"(c));
    return d;
}
__device__ __forceinline__ ull add2(ull a, ull b) {
    ull d;
    asm("add.rn.f32x2 %0, %1, %2;" : "=l"(d) : "l"(a), "l"(b));
    return d;
}
__device__ __forceinline__ ull pack2(float v) {
    ull r;
    asm("mov.b64 %0, {%1, %1};" : "=l"(r) : "f"(v));
    return r;
}
__device__ __forceinline__ float2 unpack2(ull v) {
    float2 r;
    asm("mov.b64 {%0, %1}, %2;" : "=f"(r.x), "=f"(r.y) : "l"(v));
    return r;
}
// pack two fp32 into bf16x2 word (lo -> low half), round-to-nearest
__device__ __forceinline__ unsigned f2_to_bf2(float lo, float hi) {
    unsigned r;
    asm("cvt.rn.bf16x2.f32 %0, %1, %2;" : "=r"(r) : "f"(hi), "f"(lo));
    return r;
}
// expand bf16x2 word -> packed f32x2 (shift for low lane; raw word as high,
// <1 bf16-ulp contamination in high lane)
__device__ __forceinline__ ull bf2_to_f32x2(unsigned p) {
    unsigned lo = p << 16;
    ull r;
    asm("mov.b64 %0, {%1, %2};" : "=l"(r) : "r"(lo), "r"(p));
    return r;
}
__device__ __forceinline__ void red_add_v4(float* addr, float a, float b, float c, float d) {
    asm volatile("red.global.add.v4.f32 [%0], {%1, %2, %3, %4};"
                 :: "l"(addr), "f"(a), "f"(b), "f"(c), "f"(d) : "memory");
}
__device__ __forceinline__ float sigmoid_t(float x) {
    float t;
    asm("tanh.approx.f32 %0, %1;" : "=f"(t) : "f"(0.5f * x));
    return fmaf(0.5f, t, 0.5f);
}
__device__ __forceinline__ float msg_fn(float f, float s) {
    float sp = fmaxf(s, 0.f) + __logf(1.f + __expf(-fabsf(s)));
    return sigmoid_t(f) * sp;
}

// ---------------------------------------------------------------------------
// g_eat[k][e] = relu(edge_attr @ short_w + short_b), transposed store
__global__ __launch_bounds__(256) void ea_kernel(
    const float* __restrict__ attr, const float* __restrict__ sw,
    const float* __restrict__ sb, int E)
{
    __shared__ float w[NG * SL];
    __shared__ float b[SL];
    int tid = threadIdx.x;
    if (tid < NG * SL) w[tid] = sw[tid];
    if (tid < SL)      b[tid] = sb[tid];
    __syncthreads();
    int stride = gridDim.x * blockDim.x;
    for (int e = blockIdx.x * blockDim.x + tid; e < E; e += stride) {
        float a[NG];
#pragma unroll
        for (int g = 0; g < NG; g++) a[g] = __ldg(attr + (size_t)e * NG + g);
#pragma unroll
        for (int k = 0; k < SL; k++) {
            float acc = b[k];
#pragma unroll
            for (int g = 0; g < NG; g++)
                acc = fmaf(a[g], w[g * SL + k], acc);
            g_eat[(size_t)k * EP + e] = fmaxf(acc, 0.f);
        }
    }
}

// ---------------------------------------------------------------------------
// out = relu(h @ W + b)   [N,64]
__global__ __launch_bounds__(256) void lin0_kernel(
    const float* __restrict__ h, const float* __restrict__ W,
    const float* __restrict__ b, float* __restrict__ out, int N)
{
    __shared__ float sW[64 * 64];
    __shared__ float sb[64];
    int tid = threadIdx.x;
    for (int i = tid; i < 64 * 64; i += 256) sW[i] = W[i];
    if (tid < 64) sb[tid] = b[tid];
    __syncthreads();

    int c = tid & 63, rr = tid >> 6;
    for (int r0 = blockIdx.x * 4; r0 < N; r0 += gridDim.x * 4) {
        int r = r0 + rr;
        if (r < N) {
            const float* hr = h + (size_t)r * 64;
            float acc = sb[c];
#pragma unroll 16
            for (int k = 0; k < 64; k++)
                acc = fmaf(__ldg(hr + k), sW[k * 64 + c], acc);
            out[(size_t)r * 64 + c] = fmaxf(acc, 0.f);
        }
    }
}

// ---------------------------------------------------------------------------
// g_proj[n] = out[n] @ [W1f | W2f | W1s | W2s]  (+bf on Af, +bs on As)
// Layout per node (256 floats): [Af | Bf | As | Bs].
// Also zeroes g_agg and g_sums for the layer (grid-stride prologue).
__global__ __launch_bounds__(256) void node_proj_kernel(
    const float* __restrict__ out,
    const float* __restrict__ Wf, const float* __restrict__ bf,
    const float* __restrict__ Ws, const float* __restrict__ bs,
    int N)
{
    int tid = threadIdx.x;
    // zero agg + sums
    {
        float4 z = make_float4(0.f, 0.f, 0.f, 0.f);
        float4* a4 = (float4*)g_agg;
        int total = N * 16;
        int stride = gridDim.x * 256;
        for (int i = blockIdx.x * 256 + tid; i < total; i += stride) a4[i] = z;
        if (blockIdx.x == 0 && tid < 2 * NF) g_sums[tid] = 0.f;
    }

    __shared__ __align__(16) float sOut[16 * 64];
    int c = tid;
    const float* base; int col; float bias;
    if (c < 64)       { base = Wf;           col = c;        bias = __ldg(bf + c); }
    else if (c < 128) { base = Wf + 64 * 64; col = c - 64;   bias = 0.f; }
    else if (c < 192) { base = Ws;           col = c - 128;  bias = __ldg(bs + c - 128); }
    else              { base = Ws + 64 * 64; col = c - 192;  bias = 0.f; }
    float w[64];
#pragma unroll
    for (int k = 0; k < 64; k++) w[k] = __ldg(base + k * 64 + col);

    for (int r0 = blockIdx.x * 16; r0 < N; r0 += gridDim.x * 16) {
        __syncthreads();
        for (int i = tid; i < 16 * 16; i += 256) {
            int r = i >> 4, q = i & 15;
            int rr = r0 + r;
            float4 v = (rr < N) ? ((const float4*)out)[(size_t)rr * 16 + q]
                                : make_float4(0.f, 0.f, 0.f, 0.f);
            ((float4*)sOut)[r * 16 + q] = v;
        }
        __syncthreads();
        float acc[16];
#pragma unroll
        for (int r = 0; r < 16; r++) acc[r] = bias;
#pragma unroll
        for (int k4 = 0; k4 < 16; k4++) {
#pragma unroll
            for (int r = 0; r < 16; r++) {
                float4 z = ((const float4*)sOut)[r * 16 + k4];
                acc[r] = fmaf(z.x, w[k4 * 4 + 0], acc[r]);
                acc[r] = fmaf(z.y, w[k4 * 4 + 1], acc[r]);
                acc[r] = fmaf(z.z, w[k4 * 4 + 2], acc[r]);
                acc[r] = fmaf(z.w, w[k4 * 4 + 3], acc[r]);
            }
        }
#pragma unroll
        for (int r = 0; r < 16; r++) {
            int rr = r0 + r;
            if (rr < N) g_proj[(size_t)rr * 256 + c] = acc[r];
        }
    }
}

// ---------------------------------------------------------------------------
// Edge kernel: 8 edges per warp-iter (4 slots per half-warp). bf16 interleaved
// weights in smem: one LDS.128 per k serves all 8 edges. ea TRANSPOSED: per k
// two broadcast LDG.128 fetch all 8 edges' values. fp32 proj gathers (data-
// minimal). fp32 f32x2 accumulation; msg = sigmoid_tanh(f)*softplus(s);
// red.v4 scatter (one instruction covers 2 edges via half-split).
__global__ __launch_bounds__(256) void edge_kernel(
    const int* __restrict__ ei,
    const float* __restrict__ W3f, const float* __restrict__ W3s,
    int E)
{
    __shared__ __align__(16) uint4 sWH[SL * 16];
    int tid = threadIdx.x;
    for (int i = tid; i < SL * 16; i += 256) {
        int k = i >> 4, t4 = (i & 15) * 4;
        const float* wf = W3f + k * 64 + t4;
        const float* ws = W3s + k * 64 + t4;
        uint4 v;
        v.x = f2_to_bf2(__ldg(wf + 0), __ldg(wf + 1));
        v.y = f2_to_bf2(__ldg(wf + 2), __ldg(wf + 3));
        v.z = f2_to_bf2(__ldg(ws + 0), __ldg(ws + 1));
        v.w = f2_to_bf2(__ldg(ws + 2), __ldg(ws + 3));
        sWH[i] = v;
    }
    __syncthreads();

    int lane = tid & 31;
    int t = lane & 15;
    int half = lane >> 4;

    long warp  = ((long)blockIdx.x * 256 + tid) >> 5;
    long nwarp = ((long)gridDim.x * 256) >> 5;
    long noct  = ((long)E + 7) >> 3;

    for (long g = warp; g < noct; g += nwarp) {
        long e0 = 8 * g;

        // slots: this lane's edge for slot j is e0 + 2*j + half
        bool v0, v1, v2, v3;
        int dst0, dst1, dst2, dst3;
        ull f01[4], f23[4], s01[4], s23[4];
        {
            long e;
            e = e0 + 0 + half; v0 = e < E; long ec0 = v0 ? e : e0;
            e = e0 + 2 + half; v1 = e < E; long ec1 = v1 ? e : e0;
            e = e0 + 4 + half; v2 = e < E; long ec2 = v2 ? e : e0;
            e = e0 + 6 + half; v3 = e < E; long ec3 = v3 ? e : e0;

            int src0 = __ldg(ei + ec0); dst0 = __ldg(ei + E + ec0);
            int src1 = __ldg(ei + ec1); dst1 = __ldg(ei + E + ec1);
            int src2 = __ldg(ei + ec2); dst2 = __ldg(ei + E + ec2);
            int src3 = __ldg(ei + ec3); dst3 = __ldg(ei + E + ec3);

            const ulonglong2* pd0 = (const ulonglong2*)(g_proj + (size_t)dst0 * 256);
            const ulonglong2* ps0 = (const ulonglong2*)(g_proj + (size_t)src0 * 256);
            const ulonglong2* pd1 = (const ulonglong2*)(g_proj + (size_t)dst1 * 256);
            const ulonglong2* ps1 = (const ulonglong2*)(g_proj + (size_t)src1 * 256);
            const ulonglong2* pd2 = (const ulonglong2*)(g_proj + (size_t)dst2 * 256);
            const ulonglong2* ps2 = (const ulonglong2*)(g_proj + (size_t)src2 * 256);
            const ulonglong2* pd3 = (const ulonglong2*)(g_proj + (size_t)dst3 * 256);
            const ulonglong2* ps3 = (const ulonglong2*)(g_proj + (size_t)src3 * 256);

            ulonglong2 af0 = __ldg(pd0 + t),      bf0 = __ldg(ps0 + 16 + t);
            ulonglong2 as0 = __ldg(pd0 + 32 + t), bs0 = __ldg(ps0 + 48 + t);
            ulonglong2 af1 = __ldg(pd1 + t),      bf1 = __ldg(ps1 + 16 + t);
            ulonglong2 as1 = __ldg(pd1 + 32 + t), bs1 = __ldg(ps1 + 48 + t);
            ulonglong2 af2 = __ldg(pd2 + t),      bf2 = __ldg(ps2 + 16 + t);
            ulonglong2 as2 = __ldg(pd2 + 32 + t), bs2 = __ldg(ps2 + 48 + t);
            ulonglong2 af3 = __ldg(pd3 + t),      bf3 = __ldg(ps3 + 16 + t);
            ulonglong2 as3 = __ldg(pd3 + 32 + t), bs3 = __ldg(ps3 + 48 + t);

            f01[0] = add2(af0.x, bf0.x); f23[0] = add2(af0.y, bf0.y);
            s01[0] = add2(as0.x, bs0.x); s23[0] = add2(as0.y, bs0.y);
            f01[1] = add2(af1.x, bf1.x); f23[1] = add2(af1.y, bf1.y);
            s01[1] = add2(as1.x, bs1.x); s23[1] = add2(as1.y, bs1.y);
            f01[2] = add2(af2.x, bf2.x); f23[2] = add2(af2.y, bf2.y);
            s01[2] = add2(as2.x, bs2.x); s23[2] = add2(as2.y, bs2.y);
            f01[3] = add2(af3.x, bf3.x); f23[3] = add2(af3.y, bf3.y);
            s01[3] = add2(as3.x, bs3.x); s23[3] = add2(as3.y, bs3.y);
        }

        // k loop, chunked by 4: broadcast-load 8 edges' ea values per k
#pragma unroll
        for (int kk = 0; kk < 5; kk++) {
            float4 lo[4], hi[4];
#pragma unroll
            for (int kr = 0; kr < 4; kr++) {
                const float* rowp = g_eat + (size_t)(kk * 4 + kr) * EP + e0;
                lo[kr] = __ldg((const float4*)rowp);
                hi[kr] = __ldg((const float4*)(rowp + 4));
            }
#pragma unroll
            for (int kr = 0; kr < 4; kr++) {
                int k = kk * 4 + kr;
                uint4 wp = sWH[k * 16 + t];
                ull wf01 = bf2_to_f32x2(wp.x);
                ull wf23 = bf2_to_f32x2(wp.y);
                ull ws01 = bf2_to_f32x2(wp.z);
                ull ws23 = bf2_to_f32x2(wp.w);

                float e0v = half ? lo[kr].y : lo[kr].x;   // slot 0
                float e1v = half ? lo[kr].w : lo[kr].z;   // slot 1
                float e2v = half ? hi[kr].y : hi[kr].x;   // slot 2
                float e3v = half ? hi[kr].w : hi[kr].z;   // slot 3
                ull a0 = pack2(e0v), a1 = pack2(e1v);
                ull a2 = pack2(e2v), a3 = pack2(e3v);

                f01[0] = fma2(a0, wf01, f01[0]); f23[0] = fma2(a0, wf23, f23[0]);
                s01[0] = fma2(a0, ws01, s01[0]); s23[0] = fma2(a0, ws23, s23[0]);
                f01[1] = fma2(a1, wf01, f01[1]); f23[1] = fma2(a1, wf23, f23[1]);
                s01[1] = fma2(a1, ws01, s01[1]); s23[1] = fma2(a1, ws23, s23[1]);
                f01[2] = fma2(a2, wf01, f01[2]); f23[2] = fma2(a2, wf23, f23[2]);
                s01[2] = fma2(a2, ws01, s01[2]); s23[2] = fma2(a2, ws23, s23[2]);
                f01[3] = fma2(a3, wf01, f01[3]); f23[3] = fma2(a3, wf23, f23[3]);
                s01[3] = fma2(a3, ws01, s01[3]); s23[3] = fma2(a3, ws23, s23[3]);
            }
        }

        // epilogue
        if (v0) {
            float2 F0 = unpack2(f01[0]), F1 = unpack2(f23[0]);
            float2 S0 = unpack2(s01[0]), S1 = unpack2(s23[0]);
            red_add_v4(&g_agg[(size_t)dst0 * 64 + t * 4],
                       msg_fn(F0.x, S0.x), msg_fn(F0.y, S0.y),
                       msg_fn(F1.x, S1.x), msg_fn(F1.y, S1.y));
        }
        if (v1) {
            float2 F0 = unpack2(f01[1]), F1 = unpack2(f23[1]);
            float2 S0 = unpack2(s01[1]), S1 = unpack2(s23[1]);
            red_add_v4(&g_agg[(size_t)dst1 * 64 + t * 4],
                       msg_fn(F0.x, S0.x), msg_fn(F0.y, S0.y),
                       msg_fn(F1.x, S1.x), msg_fn(F1.y, S1.y));
        }
        if (v2) {
            float2 F0 = unpack2(f01[2]), F1 = unpack2(f23[2]);
            float2 S0 = unpack2(s01[2]), S1 = unpack2(s23[2]);
            red_add_v4(&g_agg[(size_t)dst2 * 64 + t * 4],
                       msg_fn(F0.x, S0.x), msg_fn(F0.y, S0.y),
                       msg_fn(F1.x, S1.x), msg_fn(F1.y, S1.y));
        }
        if (v3) {
            float2 F0 = unpack2(f01[3]), F1 = unpack2(f23[3]);
            float2 S0 = unpack2(s01[3]), S1 = unpack2(s23[3]);
            red_add_v4(&g_agg[(size_t)dst3 * 64 + t * 4],
                       msg_fn(F0.x, S0.x), msg_fn(F0.y, S0.y),
                       msg_fn(F1.x, S1.x), msg_fn(F1.y, S1.y));
        }
    }
}

// ---------------------------------------------------------------------------
__global__ __launch_bounds__(256) void bn_stats_kernel(int N) {
    __shared__ float4 s1[256], s2[256];
    int tid = threadIdx.x;
    const float4* a4 = (const float4*)g_agg;
    int total = N * 16;
    float4 s = make_float4(0.f, 0.f, 0.f, 0.f);
    float4 q = make_float4(0.f, 0.f, 0.f, 0.f);
    int stride = gridDim.x * 256;
    for (int i = blockIdx.x * 256 + tid; i < total; i += stride) {
        float4 v = a4[i];
        s.x += v.x; s.y += v.y; s.z += v.z; s.w += v.w;
        q.x = fmaf(v.x, v.x, q.x); q.y = fmaf(v.y, v.y, q.y);
        q.z = fmaf(v.z, v.z, q.z); q.w = fmaf(v.w, v.w, q.w);
    }
    s1[tid] = s; s2[tid] = q;
    __syncthreads();
    if (tid < 16) {
        float4 S = s1[tid], Q = s2[tid];
#pragma unroll
        for (int j = 1; j < 16; j++) {
            float4 a = s1[tid + 16 * j], b = s2[tid + 16 * j];
            S.x += a.x; S.y += a.y; S.z += a.z; S.w += a.w;
            Q.x += b.x; Q.y += b.y; Q.z += b.z; Q.w += b.w;
        }
        int c0 = tid * 4;
        atomicAdd(&g_sums[c0 + 0], S.x);
        atomicAdd(&g_sums[c0 + 1], S.y);
        atomicAdd(&g_sums[c0 + 2], S.z);
        atomicAdd(&g_sums[c0 + 3], S.w);
        atomicAdd(&g_sums[64 + c0 + 0], Q.x);
        atomicAdd(&g_sums[64 + c0 + 1], Q.y);
        atomicAdd(&g_sums[64 + c0 + 2], Q.z);
        atomicAdd(&g_sums[64 + c0 + 3], Q.w);
    }
}

// ---------------------------------------------------------------------------
// out = out + relu( BN(agg) + out )
__global__ __launch_bounds__(256) void bn_apply_kernel(
    const float* __restrict__ gamma, const float* __restrict__ beta,
    float* __restrict__ out, int N, float invN)
{
    int tid = threadIdx.x;
    int c0 = (tid & 15) * 4;
    float mul[4], add[4];
#pragma unroll
    for (int j = 0; j < 4; j++) {
        float mean = g_sums[c0 + j] * invN;
        float var  = fmaf(-mean, mean, g_sums[64 + c0 + j] * invN);
        float inv  = rsqrtf(var + BN_EPS);
        float m = inv * __ldg(gamma + c0 + j);
        mul[j] = m;
        add[j] = __ldg(beta + c0 + j) - mean * m;
    }
    float4* o4 = (float4*)out;
    const float4* a4 = (const float4*)g_agg;
    int total = N * 16;
    int stride = gridDim.x * 256;
    for (int i = blockIdx.x * 256 + tid; i < total; i += stride) {
        float4 a = a4[i], o = o4[i], r;
        float bn;
        bn = fmaf(a.x, mul[0], add[0]); r.x = o.x + fmaxf(bn + o.x, 0.f);
        bn = fmaf(a.y, mul[1], add[1]); r.y = o.y + fmaxf(bn + o.y, 0.f);
        bn = fmaf(a.z, mul[2], add[2]); r.z = o.z + fmaxf(bn + o.z, 0.f);
        bn = fmaf(a.w, mul[3], add[3]); r.w = o.w + fmaxf(bn + o.w, 0.f);
        o4[i] = r;
    }
}

// ---------------------------------------------------------------------------
extern "C" void kernel_launch(void* const* d_in, const int* in_sizes, int n_in,
                              void* d_out, int out_size)
{
    const float* h      = (const float*)d_in[0];
    const int*   ei     = (const int*)  d_in[1];
    // d_in[2] = edge_weight (unused by reference)
    const float* eattr  = (const float*)d_in[3];
    const float* lin0_w = (const float*)d_in[4];
    const float* lin0_b = (const float*)d_in[5];
    const float* shw    = (const float*)d_in[6];
    const float* shb    = (const float*)d_in[7];
    const float* linf_w = (const float*)d_in[8];
    const float* linf_b = (const float*)d_in[9];
    const float* lins_w = (const float*)d_in[10];
    const float* lins_b = (const float*)d_in[11];
    const float* gamma  = (const float*)d_in[12];
    const float* beta   = (const float*)d_in[13];

    int N = in_sizes[0] / HC;
    int E = in_sizes[1] / 2;
    float* out = (float*)d_out;
    float invN = 1.f / (float)N;

    const float* Wf0 = linf_w;
    const float* Ws0 = lins_w;
    const float* Wf1 = linf_w + (size_t)ZD * NF;
    const float* Ws1 = lins_w + (size_t)ZD * NF;

    ea_kernel<<<1184, 256>>>(eattr, shw, shb, E);                          // 1
    lin0_kernel<<<592, 256>>>(h, lin0_w, lin0_b, out, N);                  // 2

    // ---- layer 0 (edge_kernel at slot 4 for ncu capture) ----
    node_proj_kernel<<<592, 256>>>(out, Wf0, linf_b, Ws0, lins_b, N);      // 3
    edge_kernel<<<1184, 256>>>(ei, Wf0 + 128 * NF, Ws0 + 128 * NF, E);     // 4
    bn_stats_kernel<<<592, 256>>>(N);                                      // 5
    bn_apply_kernel<<<592, 256>>>(gamma, beta, out, N, invN);              // 6

    // ---- layer 1 ----
    node_proj_kernel<<<592, 256>>>(out, Wf1, linf_b + NF, Ws1, lins_b + NF, N); // 7
    edge_kernel<<<1184, 256>>>(ei, Wf1 + 128 * NF, Ws1 + 128 * NF, E);          // 8
    bn_stats_kernel<<<592, 256>>>(N);                                           // 9
    bn_apply_kernel<<<592, 256>>>(gamma + NF, beta + NF, out, N, invN);         // 10
}

// round 16
// speedup vs baseline: 1.5637x; 1.0193x over previous
#include <cuda_runtime.h>
#include <math.h>

#define HC 64
#define NF 64
#define NG 5
#define SL 20
#define ZD 148
#define BN_EPS 1e-5f
#define MAX_N 50000
#define MAX_E 800000
#define EP (MAX_E + 8)   // padded edge stride for transposed ea

typedef unsigned long long ull;

// Scratch (allocation-free rule: __device__ globals)
__device__ __align__(16) float g_agg[MAX_N * NF];        // per-layer aggregation
__device__ __align__(16) float g_proj[MAX_N * 4 * NF];   // [N][Af|Bf|As|Bs] fp32
__device__ __align__(16) float g_eat[(size_t)SL * EP];   // TRANSPOSED ea: [k][e]
__device__ __align__(16) float g_sums[2 * NF];           // sum / sumsq

// ---------------- packed f32x2 helpers ----------------
__device__ __forceinline__ ull fma2(ull a, ull b, ull c) {
    ull d;
    asm("fma.rn.f32x2 %0, %1, %2, %3;" : "=l"(d) : "l"(a), "l"(b), "l"(c));
    return d;
}
__device__ __forceinline__ ull add2(ull a, ull b) {
    ull d;
    asm("add.rn.f32x2 %0, %1, %2;" : "=l"(d) : "l"(a), "l"(b));
    return d;
}
__device__ __forceinline__ ull pack2(float v) {
    ull r;
    asm("mov.b64 %0, {%1, %1};" : "=l"(r) : "f"(v));
    return r;
}
__device__ __forceinline__ float2 unpack2(ull v) {
    float2 r;
    asm("mov.b64 {%0, %1}, %2;" : "=f"(r.x), "=f"(r.y) : "l"(v));
    return r;
}
// pack two fp32 into bf16x2 word (lo -> low half), round-to-nearest
__device__ __forceinline__ unsigned f2_to_bf2(float lo, float hi) {
    unsigned r;
    asm("cvt.rn.bf16x2.f32 %0, %1, %2;" : "=r"(r) : "f"(hi), "f"(lo));
    return r;
}
// expand bf16x2 word -> packed f32x2 (shift for low lane; raw word as high,
// <1 bf16-ulp contamination in high lane)
__device__ __forceinline__ ull bf2_to_f32x2(unsigned p) {
    unsigned lo = p << 16;
    ull r;
    asm("mov.b64 %0, {%1, %2};" : "=l"(r) : "r"(lo), "r"(p));
    return r;
}
__device__ __forceinline__ void red_add_v4(float* addr, float a, float b, float c, float d) {
    asm volatile("red.global.add.v4.f32 [%0], {%1, %2, %3, %4};"
                 :: "l"(addr), "f"(a), "f"(b), "f"(c), "f"(d) : "memory");
}
__device__ __forceinline__ float sigmoid_t(float x) {
    float t;
    asm("tanh.approx.f32 %0, %1;" : "=f"(t) : "f"(0.5f * x));
    return fmaf(0.5f, t, 0.5f);
}
__device__ __forceinline__ float msg_fn(float f, float s) {
    float sp = fmaxf(s, 0.f) + __logf(1.f + __expf(-fabsf(s)));
    return sigmoid_t(f) * sp;
}

// ---------------------------------------------------------------------------
// g_eat[k][e] = relu(edge_attr @ short_w + short_b), transposed store
__global__ __launch_bounds__(256) void ea_kernel(
    const float* __restrict__ attr, const float* __restrict__ sw,
    const float* __restrict__ sb, int E)
{
    __shared__ float w[NG * SL];
    __shared__ float b[SL];
    int tid = threadIdx.x;
    if (tid < NG * SL) w[tid] = sw[tid];
    if (tid < SL)      b[tid] = sb[tid];
    __syncthreads();
    int stride = gridDim.x * blockDim.x;
    for (int e = blockIdx.x * blockDim.x + tid; e < E; e += stride) {
        float a[NG];
#pragma unroll
        for (int g = 0; g < NG; g++) a[g] = __ldg(attr + (size_t)e * NG + g);
#pragma unroll
        for (int k = 0; k < SL; k++) {
            float acc = b[k];
#pragma unroll
            for (int g = 0; g < NG; g++)
                acc = fmaf(a[g], w[g * SL + k], acc);
            g_eat[(size_t)k * EP + e] = fmaxf(acc, 0.f);
        }
    }
}

// ---------------------------------------------------------------------------
// out = relu(h @ W + b)   [N,64]
__global__ __launch_bounds__(256) void lin0_kernel(
    const float* __restrict__ h, const float* __restrict__ W,
    const float* __restrict__ b, float* __restrict__ out, int N)
{
    __shared__ float sW[64 * 64];
    __shared__ float sb[64];
    int tid = threadIdx.x;
    for (int i = tid; i < 64 * 64; i += 256) sW[i] = W[i];
    if (tid < 64) sb[tid] = b[tid];
    __syncthreads();

    int c = tid & 63, rr = tid >> 6;
    for (int r0 = blockIdx.x * 4; r0 < N; r0 += gridDim.x * 4) {
        int r = r0 + rr;
        if (r < N) {
            const float* hr = h + (size_t)r * 64;
            float acc = sb[c];
#pragma unroll 16
            for (int k = 0; k < 64; k++)
                acc = fmaf(__ldg(hr + k), sW[k * 64 + c], acc);
            out[(size_t)r * 64 + c] = fmaxf(acc, 0.f);
        }
    }
}

// ---------------------------------------------------------------------------
// g_proj[n] = out[n] @ [W1f | W2f | W1s | W2s]  (+bf on Af, +bs on As)
// Layout per node (256 floats): [Af | Bf | As | Bs].
// Also zeroes g_agg and g_sums for the layer (grid-stride prologue).
__global__ __launch_bounds__(256) void node_proj_kernel(
    const float* __restrict__ out,
    const float* __restrict__ Wf, const float* __restrict__ bf,
    const float* __restrict__ Ws, const float* __restrict__ bs,
    int N)
{
    int tid = threadIdx.x;
    // zero agg + sums
    {
        float4 z = make_float4(0.f, 0.f, 0.f, 0.f);
        float4* a4 = (float4*)g_agg;
        int total = N * 16;
        int stride = gridDim.x * 256;
        for (int i = blockIdx.x * 256 + tid; i < total; i += stride) a4[i] = z;
        if (blockIdx.x == 0 && tid < 2 * NF) g_sums[tid] = 0.f;
    }

    __shared__ __align__(16) float sOut[16 * 64];
    int c = tid;
    const float* base; int col; float bias;
    if (c < 64)       { base = Wf;           col = c;        bias = __ldg(bf + c); }
    else if (c < 128) { base = Wf + 64 * 64; col = c - 64;   bias = 0.f; }
    else if (c < 192) { base = Ws;           col = c - 128;  bias = __ldg(bs + c - 128); }
    else              { base = Ws + 64 * 64; col = c - 192;  bias = 0.f; }
    float w[64];
#pragma unroll
    for (int k = 0; k < 64; k++) w[k] = __ldg(base + k * 64 + col);

    for (int r0 = blockIdx.x * 16; r0 < N; r0 += gridDim.x * 16) {
        __syncthreads();
        for (int i = tid; i < 16 * 16; i += 256) {
            int r = i >> 4, q = i & 15;
            int rr = r0 + r;
            float4 v = (rr < N) ? ((const float4*)out)[(size_t)rr * 16 + q]
                                : make_float4(0.f, 0.f, 0.f, 0.f);
            ((float4*)sOut)[r * 16 + q] = v;
        }
        __syncthreads();
        float acc[16];
#pragma unroll
        for (int r = 0; r < 16; r++) acc[r] = bias;
#pragma unroll
        for (int k4 = 0; k4 < 16; k4++) {
#pragma unroll
            for (int r = 0; r < 16; r++) {
                float4 z = ((const float4*)sOut)[r * 16 + k4];
                acc[r] = fmaf(z.x, w[k4 * 4 + 0], acc[r]);
                acc[r] = fmaf(z.y, w[k4 * 4 + 1], acc[r]);
                acc[r] = fmaf(z.z, w[k4 * 4 + 2], acc[r]);
                acc[r] = fmaf(z.w, w[k4 * 4 + 3], acc[r]);
            }
        }
#pragma unroll
        for (int r = 0; r < 16; r++) {
            int rr = r0 + r;
            if (rr < N) g_proj[(size_t)rr * 256 + c] = acc[r];
        }
    }
}

// ---------------------------------------------------------------------------
// Edge kernel: 8 edges per warp-iter (4 slots per half-warp). bf16 interleaved
// weights in smem (one LDS.128 per k serves all 8 edges); ea TRANSPOSED with
// 2-k chunked broadcast loads; fp32 proj gathers. __launch_bounds__(256,3)
// caps regs at 85 -> 3 blocks/SM (24 warps) for the latency-bound regime.
__global__ __launch_bounds__(256, 3) void edge_kernel(
    const int* __restrict__ ei,
    const float* __restrict__ W3f, const float* __restrict__ W3s,
    int E)
{
    __shared__ __align__(16) uint4 sWH[SL * 16];
    int tid = threadIdx.x;
    for (int i = tid; i < SL * 16; i += 256) {
        int k = i >> 4, t4 = (i & 15) * 4;
        const float* wf = W3f + k * 64 + t4;
        const float* ws = W3s + k * 64 + t4;
        uint4 v;
        v.x = f2_to_bf2(__ldg(wf + 0), __ldg(wf + 1));
        v.y = f2_to_bf2(__ldg(wf + 2), __ldg(wf + 3));
        v.z = f2_to_bf2(__ldg(ws + 0), __ldg(ws + 1));
        v.w = f2_to_bf2(__ldg(ws + 2), __ldg(ws + 3));
        sWH[i] = v;
    }
    __syncthreads();

    int lane = tid & 31;
    int t = lane & 15;
    int half = lane >> 4;

    long warp  = ((long)blockIdx.x * 256 + tid) >> 5;
    long nwarp = ((long)gridDim.x * 256) >> 5;
    long noct  = ((long)E + 7) >> 3;

    for (long g = warp; g < noct; g += nwarp) {
        long e0 = 8 * g;

        bool v0, v1, v2, v3;
        int dst0, dst1, dst2, dst3;
        ull f01[4], f23[4], s01[4], s23[4];
        {
            long e;
            e = e0 + 0 + half; v0 = e < E; long ec0 = v0 ? e : e0;
            e = e0 + 2 + half; v1 = e < E; long ec1 = v1 ? e : e0;
            e = e0 + 4 + half; v2 = e < E; long ec2 = v2 ? e : e0;
            e = e0 + 6 + half; v3 = e < E; long ec3 = v3 ? e : e0;

            int src0 = __ldg(ei + ec0); dst0 = __ldg(ei + E + ec0);
            int src1 = __ldg(ei + ec1); dst1 = __ldg(ei + E + ec1);
            int src2 = __ldg(ei + ec2); dst2 = __ldg(ei + E + ec2);
            int src3 = __ldg(ei + ec3); dst3 = __ldg(ei + E + ec3);

            const ulonglong2* pd0 = (const ulonglong2*)(g_proj + (size_t)dst0 * 256);
            const ulonglong2* ps0 = (const ulonglong2*)(g_proj + (size_t)src0 * 256);
            const ulonglong2* pd1 = (const ulonglong2*)(g_proj + (size_t)dst1 * 256);
            const ulonglong2* ps1 = (const ulonglong2*)(g_proj + (size_t)src1 * 256);
            const ulonglong2* pd2 = (const ulonglong2*)(g_proj + (size_t)dst2 * 256);
            const ulonglong2* ps2 = (const ulonglong2*)(g_proj + (size_t)src2 * 256);
            const ulonglong2* pd3 = (const ulonglong2*)(g_proj + (size_t)dst3 * 256);
            const ulonglong2* ps3 = (const ulonglong2*)(g_proj + (size_t)src3 * 256);

            ulonglong2 af0 = __ldg(pd0 + t),      bf0 = __ldg(ps0 + 16 + t);
            ulonglong2 as0 = __ldg(pd0 + 32 + t), bs0 = __ldg(ps0 + 48 + t);
            ulonglong2 af1 = __ldg(pd1 + t),      bf1 = __ldg(ps1 + 16 + t);
            ulonglong2 as1 = __ldg(pd1 + 32 + t), bs1 = __ldg(ps1 + 48 + t);
            ulonglong2 af2 = __ldg(pd2 + t),      bf2 = __ldg(ps2 + 16 + t);
            ulonglong2 as2 = __ldg(pd2 + 32 + t), bs2 = __ldg(ps2 + 48 + t);
            ulonglong2 af3 = __ldg(pd3 + t),      bf3 = __ldg(ps3 + 16 + t);
            ulonglong2 as3 = __ldg(pd3 + 32 + t), bs3 = __ldg(ps3 + 48 + t);

            f01[0] = add2(af0.x, bf0.x); f23[0] = add2(af0.y, bf0.y);
            s01[0] = add2(as0.x, bs0.x); s23[0] = add2(as0.y, bs0.y);
            f01[1] = add2(af1.x, bf1.x); f23[1] = add2(af1.y, bf1.y);
            s01[1] = add2(as1.x, bs1.x); s23[1] = add2(as1.y, bs1.y);
            f01[2] = add2(af2.x, bf2.x); f23[2] = add2(af2.y, bf2.y);
            s01[2] = add2(as2.x, bs2.x); s23[2] = add2(as2.y, bs2.y);
            f01[3] = add2(af3.x, bf3.x); f23[3] = add2(af3.y, bf3.y);
            s01[3] = add2(as3.x, bs3.x); s23[3] = add2(as3.y, bs3.y);
        }

        // k loop, chunked by 2: broadcast-load 8 edges' ea values per k
#pragma unroll
        for (int kk = 0; kk < 10; kk++) {
            float4 lo[2], hi[2];
#pragma unroll
            for (int kr = 0; kr < 2; kr++) {
                const float* rowp = g_eat + (size_t)(kk * 2 + kr) * EP + e0;
                lo[kr] = __ldg((const float4*)rowp);
                hi[kr] = __ldg((const float4*)(rowp + 4));
            }
#pragma unroll
            for (int kr = 0; kr < 2; kr++) {
                int k = kk * 2 + kr;
                uint4 wp = sWH[k * 16 + t];
                ull wf01 = bf2_to_f32x2(wp.x);
                ull wf23 = bf2_to_f32x2(wp.y);
                ull ws01 = bf2_to_f32x2(wp.z);
                ull ws23 = bf2_to_f32x2(wp.w);

                float e0v = half ? lo[kr].y : lo[kr].x;   // slot 0
                float e1v = half ? lo[kr].w : lo[kr].z;   // slot 1
                float e2v = half ? hi[kr].y : hi[kr].x;   // slot 2
                float e3v = half ? hi[kr].w : hi[kr].z;   // slot 3
                ull a0 = pack2(e0v), a1 = pack2(e1v);
                ull a2 = pack2(e2v), a3 = pack2(e3v);

                f01[0] = fma2(a0, wf01, f01[0]); f23[0] = fma2(a0, wf23, f23[0]);
                s01[0] = fma2(a0, ws01, s01[0]); s23[0] = fma2(a0, ws23, s23[0]);
                f01[1] = fma2(a1, wf01, f01[1]); f23[1] = fma2(a1, wf23, f23[1]);
                s01[1] = fma2(a1, ws01, s01[1]); s23[1] = fma2(a1, ws23, s23[1]);
                f01[2] = fma2(a2, wf01, f01[2]); f23[2] = fma2(a2, wf23, f23[2]);
                s01[2] = fma2(a2, ws01, s01[2]); s23[2] = fma2(a2, ws23, s23[2]);
                f01[3] = fma2(a3, wf01, f01[3]); f23[3] = fma2(a3, wf23, f23[3]);
                s01[3] = fma2(a3, ws01, s01[3]); s23[3] = fma2(a3, ws23, s23[3]);
            }
        }

        // epilogue
        if (v0) {
            float2 F0 = unpack2(f01[0]), F1 = unpack2(f23[0]);
            float2 S0 = unpack2(s01[0]), S1 = unpack2(s23[0]);
            red_add_v4(&g_agg[(size_t)dst0 * 64 + t * 4],
                       msg_fn(F0.x, S0.x), msg_fn(F0.y, S0.y),
                       msg_fn(F1.x, S1.x), msg_fn(F1.y, S1.y));
        }
        if (v1) {
            float2 F0 = unpack2(f01[1]), F1 = unpack2(f23[1]);
            float2 S0 = unpack2(s01[1]), S1 = unpack2(s23[1]);
            red_add_v4(&g_agg[(size_t)dst1 * 64 + t * 4],
                       msg_fn(F0.x, S0.x), msg_fn(F0.y, S0.y),
                       msg_fn(F1.x, S1.x), msg_fn(F1.y, S1.y));
        }
        if (v2) {
            float2 F0 = unpack2(f01[2]), F1 = unpack2(f23[2]);
            float2 S0 = unpack2(s01[2]), S1 = unpack2(s23[2]);
            red_add_v4(&g_agg[(size_t)dst2 * 64 + t * 4],
                       msg_fn(F0.x, S0.x), msg_fn(F0.y, S0.y),
                       msg_fn(F1.x, S1.x), msg_fn(F1.y, S1.y));
        }
        if (v3) {
            float2 F0 = unpack2(f01[3]), F1 = unpack2(f23[3]);
            float2 S0 = unpack2(s01[3]), S1 = unpack2(s23[3]);
            red_add_v4(&g_agg[(size_t)dst3 * 64 + t * 4],
                       msg_fn(F0.x, S0.x), msg_fn(F0.y, S0.y),
                       msg_fn(F1.x, S1.x), msg_fn(F1.y, S1.y));
        }
    }
}

// ---------------------------------------------------------------------------
__global__ __launch_bounds__(256) void bn_stats_kernel(int N) {
    __shared__ float4 s1[256], s2[256];
    int tid = threadIdx.x;
    const float4* a4 = (const float4*)g_agg;
    int total = N * 16;
    float4 s = make_float4(0.f, 0.f, 0.f, 0.f);
    float4 q = make_float4(0.f, 0.f, 0.f, 0.f);
    int stride = gridDim.x * 256;
    for (int i = blockIdx.x * 256 + tid; i < total; i += stride) {
        float4 v = a4[i];
        s.x += v.x; s.y += v.y; s.z += v.z; s.w += v.w;
        q.x = fmaf(v.x, v.x, q.x); q.y = fmaf(v.y, v.y, q.y);
        q.z = fmaf(v.z, v.z, q.z); q.w = fmaf(v.w, v.w, q.w);
    }
    s1[tid] = s; s2[tid] = q;
    __syncthreads();
    if (tid < 16) {
        float4 S = s1[tid], Q = s2[tid];
#pragma unroll
        for (int j = 1; j < 16; j++) {
            float4 a = s1[tid + 16 * j], b = s2[tid + 16 * j];
            S.x += a.x; S.y += a.y; S.z += a.z; S.w += a.w;
            Q.x += b.x; Q.y += b.y; Q.z += b.z; Q.w += b.w;
        }
        int c0 = tid * 4;
        atomicAdd(&g_sums[c0 + 0], S.x);
        atomicAdd(&g_sums[c0 + 1], S.y);
        atomicAdd(&g_sums[c0 + 2], S.z);
        atomicAdd(&g_sums[c0 + 3], S.w);
        atomicAdd(&g_sums[64 + c0 + 0], Q.x);
        atomicAdd(&g_sums[64 + c0 + 1], Q.y);
        atomicAdd(&g_sums[64 + c0 + 2], Q.z);
        atomicAdd(&g_sums[64 + c0 + 3], Q.w);
    }
}

// ---------------------------------------------------------------------------
// out = out + relu( BN(agg) + out )
__global__ __launch_bounds__(256) void bn_apply_kernel(
    const float* __restrict__ gamma, const float* __restrict__ beta,
    float* __restrict__ out, int N, float invN)
{
    int tid = threadIdx.x;
    int c0 = (tid & 15) * 4;
    float mul[4], add[4];
#pragma unroll
    for (int j = 0; j < 4; j++) {
        float mean = g_sums[c0 + j] * invN;
        float var  = fmaf(-mean, mean, g_sums[64 + c0 + j] * invN);
        float inv  = rsqrtf(var + BN_EPS);
        float m = inv * __ldg(gamma + c0 + j);
        mul[j] = m;
        add[j] = __ldg(beta + c0 + j) - mean * m;
    }
    float4* o4 = (float4*)out;
    const float4* a4 = (const float4*)g_agg;
    int total = N * 16;
    int stride = gridDim.x * 256;
    for (int i = blockIdx.x * 256 + tid; i < total; i += stride) {
        float4 a = a4[i], o = o4[i], r;
        float bn;
        bn = fmaf(a.x, mul[0], add[0]); r.x = o.x + fmaxf(bn + o.x, 0.f);
        bn = fmaf(a.y, mul[1], add[1]); r.y = o.y + fmaxf(bn + o.y, 0.f);
        bn = fmaf(a.z, mul[2], add[2]); r.z = o.z + fmaxf(bn + o.z, 0.f);
        bn = fmaf(a.w, mul[3], add[3]); r.w = o.w + fmaxf(bn + o.w, 0.f);
        o4[i] = r;
    }
}

// ---------------------------------------------------------------------------
extern "C" void kernel_launch(void* const* d_in, const int* in_sizes, int n_in,
                              void* d_out, int out_size)
{
    const float* h      = (const float*)d_in[0];
    const int*   ei     = (const int*)  d_in[1];
    // d_in[2] = edge_weight (unused by reference)
    const float* eattr  = (const float*)d_in[3];
    const float* lin0_w = (const float*)d_in[4];
    const float* lin0_b = (const float*)d_in[5];
    const float* shw    = (const float*)d_in[6];
    const float* shb    = (const float*)d_in[7];
    const float* linf_w = (const float*)d_in[8];
    const float* linf_b = (const float*)d_in[9];
    const float* lins_w = (const float*)d_in[10];
    const float* lins_b = (const float*)d_in[11];
    const float* gamma  = (const float*)d_in[12];
    const float* beta   = (const float*)d_in[13];

    int N = in_sizes[0] / HC;
    int E = in_sizes[1] / 2;
    float* out = (float*)d_out;
    float invN = 1.f / (float)N;

    const float* Wf0 = linf_w;
    const float* Ws0 = lins_w;
    const float* Wf1 = linf_w + (size_t)ZD * NF;
    const float* Ws1 = lins_w + (size_t)ZD * NF;

    ea_kernel<<<1184, 256>>>(eattr, shw, shb, E);                          // 1
    lin0_kernel<<<592, 256>>>(h, lin0_w, lin0_b, out, N);                  // 2

    // ---- layer 0 (edge_kernel at slot 4 for ncu capture) ----
    node_proj_kernel<<<592, 256>>>(out, Wf0, linf_b, Ws0, lins_b, N);      // 3
    edge_kernel<<<1332, 256>>>(ei, Wf0 + 128 * NF, Ws0 + 128 * NF, E);     // 4
    bn_stats_kernel<<<592, 256>>>(N);                                      // 5
    bn_apply_kernel<<<592, 256>>>(gamma, beta, out, N, invN);              // 6

    // ---- layer 1 ----
    node_proj_kernel<<<592, 256>>>(out, Wf1, linf_b + NF, Ws1, lins_b + NF, N); // 7
    edge_kernel<<<1332, 256>>>(ei, Wf1 + 128 * NF, Ws1 + 128 * NF, E);          // 8
    bn_stats_kernel<<<592, 256>>>(N);                                           // 9
    bn_apply_kernel<<<592, 256>>>(gamma + NF, beta + NF, out, N, invN);         // 10
}

// round 17
// speedup vs baseline: 1.8307x; 1.1707x over previous
#include <cuda_runtime.h>
#include <math.h>

#define HC 64
#define NF 64
#define NG 5
#define SL 20
#define ZD 148
#define BN_EPS 1e-5f
#define MAX_N 50000
#define MAX_E 800000
#define EP (MAX_E + 8)   // padded edge stride for transposed ea

typedef unsigned long long ull;

// Scratch (allocation-free rule: __device__ globals)
__device__ __align__(16) float g_agg[MAX_N * NF];        // per-layer aggregation
__device__ __align__(16) float g_proj[MAX_N * 4 * NF];   // [N][Af|Bf|As|Bs] fp32
__device__ __align__(16) float g_eat[(size_t)SL * EP];   // TRANSPOSED ea: [k][e]
__device__ __align__(16) float g_sums[2 * NF];           // sum / sumsq

// ---------------- packed f32x2 helpers ----------------
__device__ __forceinline__ ull fma2(ull a, ull b, ull c) {
    ull d;
    asm("fma.rn.f32x2 %0, %1, %2, %3;" : "=l"(d) : "l"(a), "l"(b), "l"(c));
    return d;
}
__device__ __forceinline__ ull add2(ull a, ull b) {
    ull d;
    asm("add.rn.f32x2 %0, %1, %2;" : "=l"(d) : "l"(a), "l"(b));
    return d;
}
__device__ __forceinline__ ull pack2(float v) {
    ull r;
    asm("mov.b64 %0, {%1, %1};" : "=l"(r) : "f"(v));
    return r;
}
__device__ __forceinline__ float2 unpack2(ull v) {
    float2 r;
    asm("mov.b64 {%0, %1}, %2;" : "=f"(r.x), "=f"(r.y) : "l"(v));
    return r;
}
__device__ __forceinline__ void red_add_v4(float* addr, float a, float b, float c, float d) {
    asm volatile("red.global.add.v4.f32 [%0], {%1, %2, %3, %4};"
                 :: "l"(addr), "f"(a), "f"(b), "f"(c), "f"(d) : "memory");
}
__device__ __forceinline__ float sigmoid_t(float x) {
    float t;
    asm("tanh.approx.f32 %0, %1;" : "=f"(t) : "f"(0.5f * x));
    return fmaf(0.5f, t, 0.5f);
}
__device__ __forceinline__ float msg_fn(float f, float s) {
    float sp = fmaxf(s, 0.f) + __logf(1.f + __expf(-fabsf(s)));
    return sigmoid_t(f) * sp;
}

// ---------------------------------------------------------------------------
// g_eat[k][e] = relu(edge_attr @ short_w + short_b), transposed store
__global__ __launch_bounds__(256) void ea_kernel(
    const float* __restrict__ attr, const float* __restrict__ sw,
    const float* __restrict__ sb, int E)
{
    __shared__ float w[NG * SL];
    __shared__ float b[SL];
    int tid = threadIdx.x;
    if (tid < NG * SL) w[tid] = sw[tid];
    if (tid < SL)      b[tid] = sb[tid];
    __syncthreads();
    int stride = gridDim.x * blockDim.x;
    for (int e = blockIdx.x * blockDim.x + tid; e < E; e += stride) {
        float a[NG];
#pragma unroll
        for (int g = 0; g < NG; g++) a[g] = __ldg(attr + (size_t)e * NG + g);
#pragma unroll
        for (int k = 0; k < SL; k++) {
            float acc = b[k];
#pragma unroll
            for (int g = 0; g < NG; g++)
                acc = fmaf(a[g], w[g * SL + k], acc);
            g_eat[(size_t)k * EP + e] = fmaxf(acc, 0.f);
        }
    }
}

// ---------------------------------------------------------------------------
// out = relu(h @ W + b)   [N,64]
__global__ __launch_bounds__(256) void lin0_kernel(
    const float* __restrict__ h, const float* __restrict__ W,
    const float* __restrict__ b, float* __restrict__ out, int N)
{
    __shared__ float sW[64 * 64];
    __shared__ float sb[64];
    int tid = threadIdx.x;
    for (int i = tid; i < 64 * 64; i += 256) sW[i] = W[i];
    if (tid < 64) sb[tid] = b[tid];
    __syncthreads();

    int c = tid & 63, rr = tid >> 6;
    for (int r0 = blockIdx.x * 4; r0 < N; r0 += gridDim.x * 4) {
        int r = r0 + rr;
        if (r < N) {
            const float* hr = h + (size_t)r * 64;
            float acc = sb[c];
#pragma unroll 16
            for (int k = 0; k < 64; k++)
                acc = fmaf(__ldg(hr + k), sW[k * 64 + c], acc);
            out[(size_t)r * 64 + c] = fmaxf(acc, 0.f);
        }
    }
}

// ---------------------------------------------------------------------------
// g_proj[n] = out[n] @ [W1f | W2f | W1s | W2s]  (+bf on Af, +bs on As)
// Layout per node (256 floats): [Af | Bf | As | Bs].
// Also zeroes g_agg and g_sums for the layer (grid-stride prologue).
__global__ __launch_bounds__(256) void node_proj_kernel(
    const float* __restrict__ out,
    const float* __restrict__ Wf, const float* __restrict__ bf,
    const float* __restrict__ Ws, const float* __restrict__ bs,
    int N)
{
    int tid = threadIdx.x;
    // zero agg + sums
    {
        float4 z = make_float4(0.f, 0.f, 0.f, 0.f);
        float4* a4 = (float4*)g_agg;
        int total = N * 16;
        int stride = gridDim.x * 256;
        for (int i = blockIdx.x * 256 + tid; i < total; i += stride) a4[i] = z;
        if (blockIdx.x == 0 && tid < 2 * NF) g_sums[tid] = 0.f;
    }

    __shared__ __align__(16) float sOut[16 * 64];
    int c = tid;
    const float* base; int col; float bias;
    if (c < 64)       { base = Wf;           col = c;        bias = __ldg(bf + c); }
    else if (c < 128) { base = Wf + 64 * 64; col = c - 64;   bias = 0.f; }
    else if (c < 192) { base = Ws;           col = c - 128;  bias = __ldg(bs + c - 128); }
    else              { base = Ws + 64 * 64; col = c - 192;  bias = 0.f; }
    float w[64];
#pragma unroll
    for (int k = 0; k < 64; k++) w[k] = __ldg(base + k * 64 + col);

    for (int r0 = blockIdx.x * 16; r0 < N; r0 += gridDim.x * 16) {
        __syncthreads();
        for (int i = tid; i < 16 * 16; i += 256) {
            int r = i >> 4, q = i & 15;
            int rr = r0 + r;
            float4 v = (rr < N) ? ((const float4*)out)[(size_t)rr * 16 + q]
                                : make_float4(0.f, 0.f, 0.f, 0.f);
            ((float4*)sOut)[r * 16 + q] = v;
        }
        __syncthreads();
        float acc[16];
#pragma unroll
        for (int r = 0; r < 16; r++) acc[r] = bias;
#pragma unroll
        for (int k4 = 0; k4 < 16; k4++) {
#pragma unroll
            for (int r = 0; r < 16; r++) {
                float4 z = ((const float4*)sOut)[r * 16 + k4];
                acc[r] = fmaf(z.x, w[k4 * 4 + 0], acc[r]);
                acc[r] = fmaf(z.y, w[k4 * 4 + 1], acc[r]);
                acc[r] = fmaf(z.z, w[k4 * 4 + 2], acc[r]);
                acc[r] = fmaf(z.w, w[k4 * 4 + 3], acc[r]);
            }
        }
#pragma unroll
        for (int r = 0; r < 16; r++) {
            int rr = r0 + r;
            if (rr < N) g_proj[(size_t)rr * 256 + c] = acc[r];
        }
    }
}

// ---------------------------------------------------------------------------
// Edge kernel: 8 edges per warp-iter; half h owns edges e0+4h..e0+4h+3, so the
// per-k ea float4 load IS the 4 slot values (no SELs). fp32 weights in two
// conflict-free smem arrays (2x LDS.128 per k, zero expansion ALU).
// fp32 f32x2 accumulation; msg = sigmoid_tanh(f)*softplus(s); red.v4 scatter.
__global__ __launch_bounds__(256, 3) void edge_kernel(
    const int* __restrict__ ei,
    const float* __restrict__ W3f, const float* __restrict__ W3s,
    int E)
{
    // sWf[k*16+t] = {wf[4t],wf[4t+1]},{wf[4t+2],wf[4t+3]} as packed f32x2 pairs
    __shared__ __align__(16) ulonglong2 sWf[SL * 16];
    __shared__ __align__(16) ulonglong2 sWs[SL * 16];
    int tid = threadIdx.x;
    for (int i = tid; i < SL * 16; i += 256) {
        int k = i >> 4, t4 = (i & 15) * 4;
        sWf[i] = *(const ulonglong2*)(W3f + k * 64 + t4);
        sWs[i] = *(const ulonglong2*)(W3s + k * 64 + t4);
    }
    __syncthreads();

    int lane = tid & 31;
    int t = lane & 15;
    int half = lane >> 4;

    long warp  = ((long)blockIdx.x * 256 + tid) >> 5;
    long nwarp = ((long)gridDim.x * 256) >> 5;
    long noct  = ((long)E + 7) >> 3;

    for (long g = warp; g < noct; g += nwarp) {
        long e0 = 8 * g;
        long eh = e0 + 4 * half;          // this half's first edge

        bool v0, v1, v2, v3;
        int dst0, dst1, dst2, dst3;
        ull f01[4], f23[4], s01[4], s23[4];
        {
            long e;
            e = eh + 0; v0 = e < E; long ec0 = v0 ? e : e0;
            e = eh + 1; v1 = e < E; long ec1 = v1 ? e : e0;
            e = eh + 2; v2 = e < E; long ec2 = v2 ? e : e0;
            e = eh + 3; v3 = e < E; long ec3 = v3 ? e : e0;

            int src0 = __ldg(ei + ec0); dst0 = __ldg(ei + E + ec0);
            int src1 = __ldg(ei + ec1); dst1 = __ldg(ei + E + ec1);
            int src2 = __ldg(ei + ec2); dst2 = __ldg(ei + E + ec2);
            int src3 = __ldg(ei + ec3); dst3 = __ldg(ei + E + ec3);

            const ulonglong2* pd0 = (const ulonglong2*)(g_proj + (size_t)dst0 * 256);
            const ulonglong2* ps0 = (const ulonglong2*)(g_proj + (size_t)src0 * 256);
            const ulonglong2* pd1 = (const ulonglong2*)(g_proj + (size_t)dst1 * 256);
            const ulonglong2* ps1 = (const ulonglong2*)(g_proj + (size_t)src1 * 256);
            const ulonglong2* pd2 = (const ulonglong2*)(g_proj + (size_t)dst2 * 256);
            const ulonglong2* ps2 = (const ulonglong2*)(g_proj + (size_t)src2 * 256);
            const ulonglong2* pd3 = (const ulonglong2*)(g_proj + (size_t)dst3 * 256);
            const ulonglong2* ps3 = (const ulonglong2*)(g_proj + (size_t)src3 * 256);

            ulonglong2 af0 = __ldg(pd0 + t),      bf0 = __ldg(ps0 + 16 + t);
            ulonglong2 as0 = __ldg(pd0 + 32 + t), bs0 = __ldg(ps0 + 48 + t);
            ulonglong2 af1 = __ldg(pd1 + t),      bf1 = __ldg(ps1 + 16 + t);
            ulonglong2 as1 = __ldg(pd1 + 32 + t), bs1 = __ldg(ps1 + 48 + t);
            ulonglong2 af2 = __ldg(pd2 + t),      bf2 = __ldg(ps2 + 16 + t);
            ulonglong2 as2 = __ldg(pd2 + 32 + t), bs2 = __ldg(ps2 + 48 + t);
            ulonglong2 af3 = __ldg(pd3 + t),      bf3 = __ldg(ps3 + 16 + t);
            ulonglong2 as3 = __ldg(pd3 + 32 + t), bs3 = __ldg(ps3 + 48 + t);

            f01[0] = add2(af0.x, bf0.x); f23[0] = add2(af0.y, bf0.y);
            s01[0] = add2(as0.x, bs0.x); s23[0] = add2(as0.y, bs0.y);
            f01[1] = add2(af1.x, bf1.x); f23[1] = add2(af1.y, bf1.y);
            s01[1] = add2(as1.x, bs1.x); s23[1] = add2(as1.y, bs1.y);
            f01[2] = add2(af2.x, bf2.x); f23[2] = add2(af2.y, bf2.y);
            s01[2] = add2(as2.x, bs2.x); s23[2] = add2(as2.y, bs2.y);
            f01[3] = add2(af3.x, bf3.x); f23[3] = add2(af3.y, bf3.y);
            s01[3] = add2(as3.x, bs3.x); s23[3] = add2(as3.y, bs3.y);
        }

        // k loop, chunked by 2: one float4 per k = this half's 4 slot values
#pragma unroll
        for (int kk = 0; kk < 10; kk++) {
            float4 av[2];
#pragma unroll
            for (int kr = 0; kr < 2; kr++)
                av[kr] = __ldg((const float4*)(g_eat + (size_t)(kk * 2 + kr) * EP + eh));
#pragma unroll
            for (int kr = 0; kr < 2; kr++) {
                int k = kk * 2 + kr;
                ulonglong2 wf = sWf[k * 16 + t];
                ulonglong2 ws = sWs[k * 16 + t];
                ull a0 = pack2(av[kr].x), a1 = pack2(av[kr].y);
                ull a2 = pack2(av[kr].z), a3 = pack2(av[kr].w);

                f01[0] = fma2(a0, wf.x, f01[0]); f23[0] = fma2(a0, wf.y, f23[0]);
                s01[0] = fma2(a0, ws.x, s01[0]); s23[0] = fma2(a0, ws.y, s23[0]);
                f01[1] = fma2(a1, wf.x, f01[1]); f23[1] = fma2(a1, wf.y, f23[1]);
                s01[1] = fma2(a1, ws.x, s01[1]); s23[1] = fma2(a1, ws.y, s23[1]);
                f01[2] = fma2(a2, wf.x, f01[2]); f23[2] = fma2(a2, wf.y, f23[2]);
                s01[2] = fma2(a2, ws.x, s01[2]); s23[2] = fma2(a2, ws.y, s23[2]);
                f01[3] = fma2(a3, wf.x, f01[3]); f23[3] = fma2(a3, wf.y, f23[3]);
                s01[3] = fma2(a3, ws.x, s01[3]); s23[3] = fma2(a3, ws.y, s23[3]);
            }
        }

        // epilogue
        if (v0) {
            float2 F0 = unpack2(f01[0]), F1 = unpack2(f23[0]);
            float2 S0 = unpack2(s01[0]), S1 = unpack2(s23[0]);
            red_add_v4(&g_agg[(size_t)dst0 * 64 + t * 4],
                       msg_fn(F0.x, S0.x), msg_fn(F0.y, S0.y),
                       msg_fn(F1.x, S1.x), msg_fn(F1.y, S1.y));
        }
        if (v1) {
            float2 F0 = unpack2(f01[1]), F1 = unpack2(f23[1]);
            float2 S0 = unpack2(s01[1]), S1 = unpack2(s23[1]);
            red_add_v4(&g_agg[(size_t)dst1 * 64 + t * 4],
                       msg_fn(F0.x, S0.x), msg_fn(F0.y, S0.y),
                       msg_fn(F1.x, S1.x), msg_fn(F1.y, S1.y));
        }
        if (v2) {
            float2 F0 = unpack2(f01[2]), F1 = unpack2(f23[2]);
            float2 S0 = unpack2(s01[2]), S1 = unpack2(s23[2]);
            red_add_v4(&g_agg[(size_t)dst2 * 64 + t * 4],
                       msg_fn(F0.x, S0.x), msg_fn(F0.y, S0.y),
                       msg_fn(F1.x, S1.x), msg_fn(F1.y, S1.y));
        }
        if (v3) {
            float2 F0 = unpack2(f01[3]), F1 = unpack2(f23[3]);
            float2 S0 = unpack2(s01[3]), S1 = unpack2(s23[3]);
            red_add_v4(&g_agg[(size_t)dst3 * 64 + t * 4],
                       msg_fn(F0.x, S0.x), msg_fn(F0.y, S0.y),
                       msg_fn(F1.x, S1.x), msg_fn(F1.y, S1.y));
        }
    }
}

// ---------------------------------------------------------------------------
__global__ __launch_bounds__(256) void bn_stats_kernel(int N) {
    __shared__ float4 s1[256], s2[256];
    int tid = threadIdx.x;
    const float4* a4 = (const float4*)g_agg;
    int total = N * 16;
    float4 s = make_float4(0.f, 0.f, 0.f, 0.f);
    float4 q = make_float4(0.f, 0.f, 0.f, 0.f);
    int stride = gridDim.x * 256;
    for (int i = blockIdx.x * 256 + tid; i < total; i += stride) {
        float4 v = a4[i];
        s.x += v.x; s.y += v.y; s.z += v.z; s.w += v.w;
        q.x = fmaf(v.x, v.x, q.x); q.y = fmaf(v.y, v.y, q.y);
        q.z = fmaf(v.z, v.z, q.z); q.w = fmaf(v.w, v.w, q.w);
    }
    s1[tid] = s; s2[tid] = q;
    __syncthreads();
    if (tid < 16) {
        float4 S = s1[tid], Q = s2[tid];
#pragma unroll
        for (int j = 1; j < 16; j++) {
            float4 a = s1[tid + 16 * j], b = s2[tid + 16 * j];
            S.x += a.x; S.y += a.y; S.z += a.z; S.w += a.w;
            Q.x += b.x; Q.y += b.y; Q.z += b.z; Q.w += b.w;
        }
        int c0 = tid * 4;
        atomicAdd(&g_sums[c0 + 0], S.x);
        atomicAdd(&g_sums[c0 + 1], S.y);
        atomicAdd(&g_sums[c0 + 2], S.z);
        atomicAdd(&g_sums[c0 + 3], S.w);
        atomicAdd(&g_sums[64 + c0 + 0], Q.x);
        atomicAdd(&g_sums[64 + c0 + 1], Q.y);
        atomicAdd(&g_sums[64 + c0 + 2], Q.z);
        atomicAdd(&g_sums[64 + c0 + 3], Q.w);
    }
}

// ---------------------------------------------------------------------------
// out = out + relu( BN(agg) + out )
__global__ __launch_bounds__(256) void bn_apply_kernel(
    const float* __restrict__ gamma, const float* __restrict__ beta,
    float* __restrict__ out, int N, float invN)
{
    int tid = threadIdx.x;
    int c0 = (tid & 15) * 4;
    float mul[4], add[4];
#pragma unroll
    for (int j = 0; j < 4; j++) {
        float mean = g_sums[c0 + j] * invN;
        float var  = fmaf(-mean, mean, g_sums[64 + c0 + j] * invN);
        float inv  = rsqrtf(var + BN_EPS);
        float m = inv * __ldg(gamma + c0 + j);
        mul[j] = m;
        add[j] = __ldg(beta + c0 + j) - mean * m;
    }
    float4* o4 = (float4*)out;
    const float4* a4 = (const float4*)g_agg;
    int total = N * 16;
    int stride = gridDim.x * 256;
    for (int i = blockIdx.x * 256 + tid; i < total; i += stride) {
        float4 a = a4[i], o = o4[i], r;
        float bn;
        bn = fmaf(a.x, mul[0], add[0]); r.x = o.x + fmaxf(bn + o.x, 0.f);
        bn = fmaf(a.y, mul[1], add[1]); r.y = o.y + fmaxf(bn + o.y, 0.f);
        bn = fmaf(a.z, mul[2], add[2]); r.z = o.z + fmaxf(bn + o.z, 0.f);
        bn = fmaf(a.w, mul[3], add[3]); r.w = o.w + fmaxf(bn + o.w, 0.f);
        o4[i] = r;
    }
}

// ---------------------------------------------------------------------------
extern "C" void kernel_launch(void* const* d_in, const int* in_sizes, int n_in,
                              void* d_out, int out_size)
{
    const float* h      = (const float*)d_in[0];
    const int*   ei     = (const int*)  d_in[1];
    // d_in[2] = edge_weight (unused by reference)
    const float* eattr  = (const float*)d_in[3];
    const float* lin0_w = (const float*)d_in[4];
    const float* lin0_b = (const float*)d_in[5];
    const float* shw    = (const float*)d_in[6];
    const float* shb    = (const float*)d_in[7];
    const float* linf_w = (const float*)d_in[8];
    const float* linf_b = (const float*)d_in[9];
    const float* lins_w = (const float*)d_in[10];
    const float* lins_b = (const float*)d_in[11];
    const float* gamma  = (const float*)d_in[12];
    const float* beta   = (const float*)d_in[13];

    int N = in_sizes[0] / HC;
    int E = in_sizes[1] / 2;
    float* out = (float*)d_out;
    float invN = 1.f / (float)N;

    const float* Wf0 = linf_w;
    const float* Ws0 = lins_w;
    const float* Wf1 = linf_w + (size_t)ZD * NF;
    const float* Ws1 = lins_w + (size_t)ZD * NF;

    ea_kernel<<<1184, 256>>>(eattr, shw, shb, E);                          // 1
    lin0_kernel<<<592, 256>>>(h, lin0_w, lin0_b, out, N);                  // 2

    // ---- layer 0 (edge_kernel at slot 4 for ncu capture) ----
    node_proj_kernel<<<592, 256>>>(out, Wf0, linf_b, Ws0, lins_b, N);      // 3
    edge_kernel<<<1332, 256>>>(ei, Wf0 + 128 * NF, Ws0 + 128 * NF, E);     // 4
    bn_stats_kernel<<<592, 256>>>(N);                                      // 5
    bn_apply_kernel<<<592, 256>>>(gamma, beta, out, N, invN);              // 6

    // ---- layer 1 ----
    node_proj_kernel<<<592, 256>>>(out, Wf1, linf_b + NF, Ws1, lins_b + NF, N); // 7
    edge_kernel<<<1332, 256>>>(ei, Wf1 + 128 * NF, Ws1 + 128 * NF, E);          // 8
    bn_stats_kernel<<<592, 256>>>(N);                                           // 9
    bn_apply_kernel<<<592, 256>>>(gamma + NF, beta + NF, out, N, invN);         // 10
}